// round 13
// baseline (speedup 1.0000x reference)
#include <cuda_runtime.h>
#include <cstdint>

// Conv2D 15x15 valid cross-correlation, 4096x4096 fp32 -> 4082x4082 fp32.
// Banded-Toeplitz implicit GEMM, legacy mma.sync m16n8k8 tf32 (sm_80 PTX).
//
// R13 = R11 main loop (best measured: LDS.64 fragments, pitch-56 permuted A,
// deduped 3-block Toeplitz B, nt-inner MMA chains) + R12's division-free
// fills (row-strip A fill with hoisted clamp/permute; pow2-decoded B fill).
//
// Warp tile 32(oy) x 32(ox), CTA 128x32, K=48 (6 chunks of 8).
// Per warp per ky: 24 A LDS.64 + 3 B LDS.64 -> 24 MMAs (MMA(nt,jj) uses
// A chunk nt+jj). fp32 register accumulation, tf32 inputs (rel_err ~3e-4).

#define H_IN  4096
#define W_IN  4096
#define KH    15
#define KW    15
#define OH    (H_IN - KH + 1)   // 4082
#define OW    (W_IN - KW + 1)   // 4082

#define TM    128               // oy per CTA
#define TN    32                // ox per CTA
#define KDIM  48                // input cols per tile
#define NCH   6                 // k-chunks
#define AROWS (TM + KH - 1)     // 142
#define APITCH 56               // floats
#define NT    128

__device__ __forceinline__ uint32_t tf32r(float f) {
    uint32_t r; asm("cvt.rna.tf32.f32 %0, %1;" : "=r"(r) : "f"(f)); return r;
}

__device__ __forceinline__ void mma_tf32(float (&acc)[4],
                                         float2 a02, float2 a13, float2 b) {
    asm volatile(
        "mma.sync.aligned.m16n8k8.row.col.f32.tf32.tf32.f32 "
        "{%0,%1,%2,%3}, {%4,%5,%6,%7}, {%8,%9}, {%0,%1,%2,%3};"
        : "+f"(acc[0]), "+f"(acc[1]), "+f"(acc[2]), "+f"(acc[3])
        : "r"(__float_as_uint(a02.x)),   // a0: (r,   k)
          "r"(__float_as_uint(a13.x)),   // a1: (r+8, k)
          "r"(__float_as_uint(a02.y)),   // a2: (r,   k+4)
          "r"(__float_as_uint(a13.y)),   // a3: (r+8, k+4)
          "r"(__float_as_uint(b.x)),     // b0: (k,   n)
          "r"(__float_as_uint(b.y)));    // b1: (k+4, n)
}

__global__ __launch_bounds__(NT)
void conv15_hmma4_kernel(const float* __restrict__ X,
                         const float* __restrict__ Wt,
                         const float* __restrict__ bias,
                         float* __restrict__ out)
{
    __shared__ __align__(16) float sA[AROWS * APITCH];   // 31808 B
    __shared__ __align__(16) float sB[KH * 3 * 64];      // 11520 B

    const int tid  = threadIdx.x;
    const int warp = tid >> 5;
    const int lane = tid & 31;
    const int gx0  = blockIdx.x * TN;
    const int gy0  = blockIdx.y * TM;

    // ---- A fill: row strips, division-free, hoisted permute/clamp ----
    // permute within 8-col chunk: cp = (c & ~7) | ((c&3)<<1) | ((c&7)>>2)
    {
        const int c0  = lane;                          // cols 0..31
        const int cp0 = (c0 & ~7) | ((c0 & 3) << 1) | ((c0 & 7) >> 2);
        const int c1  = lane + 32;                     // cols 32..47 (lane<16)
        const int cp1 = (c1 & ~7) | ((c1 & 3) << 1) | ((c1 & 7) >> 2);
        const int gxa = min(gx0 + c0, W_IN - 1);
        const int gxb = min(gx0 + c1, W_IN - 1);
        #pragma unroll 2
        for (int r = warp; r < AROWS; r += 4) {
            const int gy = min(gy0 + r, H_IN - 1);
            const float* xr = X + (size_t)gy * W_IN;
            sA[r * APITCH + cp0] = __uint_as_float(tf32r(xr[gxa]));
            if (lane < 16)
                sA[r * APITCH + cp1] = __uint_as_float(tf32r(xr[gxb]));
        }
    }
    // ---- B fill: 15 ky x 3 jj deduped Toeplitz blocks, [n][k'] 8x8 ----
    #pragma unroll 1
    for (int ky = 0; ky < KH; ky++) {
        const float* wr = Wt + ky * KW;
        #pragma unroll
        for (int i = tid; i < 3 * 64; i += NT) {
            int jj = i >> 6, e = i & 63;
            int nl = e >> 3, kp = e & 7;
            int kl = (kp >> 1) | ((kp & 1) << 2);     // inverse permute
            int kx = jj * 8 + kl - nl;
            float v = (kx >= 0 && kx < KW) ? wr[kx] : 0.0f;
            sB[ky * 192 + i] = __uint_as_float(tf32r(v));
        }
    }
    __syncthreads();

    float acc[2][4][4];
    #pragma unroll
    for (int mt = 0; mt < 2; mt++)
        #pragma unroll
        for (int nt = 0; nt < 4; nt++)
            #pragma unroll
            for (int f = 0; f < 4; f++) acc[mt][nt][f] = 0.0f;

    const int rA   = warp * 32 + (lane >> 2);   // fragment base row (mt=0)
    const int c2   = (lane & 3) * 2;            // permuted (k,k+4) pair col
    const int bOff = (lane >> 2) * 8 + c2;      // B block: [n][k']

    #pragma unroll 1
    for (int ky = 0; ky < KH; ky++) {
        float2 Bf[3];
        #pragma unroll
        for (int jj = 0; jj < 3; jj++)
            Bf[jj] = *(const float2*)&sB[ky * 192 + jj * 64 + bOff];

        #pragma unroll
        for (int mt = 0; mt < 2; mt++) {
            const float* ap = &sA[(rA + ky + mt * 16) * APITCH + c2];
            float2 A02[NCH], A13[NCH];
            #pragma unroll
            for (int ch = 0; ch < NCH; ch++) {
                A02[ch] = *(const float2*)(ap + 8 * ch);
                A13[ch] = *(const float2*)(ap + 8 * APITCH + 8 * ch);
            }
            #pragma unroll
            for (int jj = 0; jj < 3; jj++)
                #pragma unroll
                for (int nt = 0; nt < 4; nt++)   // nt-inner: 4 indep chains
                    mma_tf32(acc[mt][nt], A02[nt + jj], A13[nt + jj], Bf[jj]);
        }
    }

    // ---- epilogue: c0,c1 -> row r; c2,c3 -> row r+8; cols nt*8 + c2 ----
    const float bv = bias[0];
    #pragma unroll
    for (int mt = 0; mt < 2; mt++) {
        #pragma unroll
        for (int half = 0; half < 2; half++) {
            int oy = gy0 + warp * 32 + 16 * mt + (lane >> 2) + 8 * half;
            if (oy < OH) {
                #pragma unroll
                for (int nt = 0; nt < 4; nt++) {
                    int ox = gx0 + 8 * nt + c2;
                    if (ox < OW) {      // ox,OW even -> pair fits
                        float2 v;
                        v.x = acc[mt][nt][2 * half]     + bv;
                        v.y = acc[mt][nt][2 * half + 1] + bv;
                        *(float2*)&out[(size_t)oy * OW + ox] = v;
                    }
                }
            }
        }
    }
}

extern "C" void kernel_launch(void* const* d_in, const int* in_sizes, int n_in,
                              void* d_out, int out_size)
{
    const float* X    = (const float*)d_in[0];  // [4096,4096]
    const float* Wt   = (const float*)d_in[1];  // [15,15]
    const float* bias = (const float*)d_in[2];  // [1]
    float* out        = (float*)d_out;          // [4082,4082]

    dim3 grid((OW + TN - 1) / TN,    // 128
              (OH + TM - 1) / TM);   // 32
    conv15_hmma4_kernel<<<grid, NT>>>(X, Wt, bias, out);
}

// round 14
// speedup vs baseline: 1.2815x; 1.2815x over previous
#include <cuda_runtime.h>
#include <cstdint>

// Conv2D 15x15 valid cross-correlation, 4096x4096 fp32 -> 4082x4082 fp32.
// Banded-Toeplitz implicit GEMM, legacy mma.sync m16n8k8 tf32 (sm_80 PTX).
//
// R14 = R11 (best measured) with the mainloop software-pipelined:
// explicit double-buffered A fragments and next-ky B fragments so every
// MMA's operands were loaded >= one 12-MMA block earlier. Schedule:
//   preload A(ky0,mt0), Bf(ky0)
//   per ky: prefetch A(ky,mt1); prefetch Bf(ky+1); MMA(mt0);
//           prefetch A(ky+1,mt0); MMA(mt1); rotate Bf.
//
// Warp tile 32(oy) x 32(ox), CTA 128x32, K=48 (6 chunks of 8).
// B deduped: 3 8x8 Toeplitz blocks per ky feed all (mt,nt). fp32 reg accum.

#define H_IN  4096
#define W_IN  4096
#define KH    15
#define KW    15
#define OH    (H_IN - KH + 1)   // 4082
#define OW    (W_IN - KW + 1)   // 4082

#define TM    128               // oy per CTA
#define TN    32                // ox per CTA
#define KDIM  48                // input cols per tile
#define NCH   6                 // k-chunks
#define AROWS (TM + KH - 1)     // 142
#define APITCH 56               // floats
#define NT    128

__device__ __forceinline__ uint32_t tf32r(float f) {
    uint32_t r; asm("cvt.rna.tf32.f32 %0, %1;" : "=r"(r) : "f"(f)); return r;
}

__device__ __forceinline__ void mma_tf32(float (&acc)[4],
                                         float2 a02, float2 a13, float2 b) {
    asm volatile(
        "mma.sync.aligned.m16n8k8.row.col.f32.tf32.tf32.f32 "
        "{%0,%1,%2,%3}, {%4,%5,%6,%7}, {%8,%9}, {%0,%1,%2,%3};"
        : "+f"(acc[0]), "+f"(acc[1]), "+f"(acc[2]), "+f"(acc[3])
        : "r"(__float_as_uint(a02.x)),   // a0: (r,   k)
          "r"(__float_as_uint(a13.x)),   // a1: (r+8, k)
          "r"(__float_as_uint(a02.y)),   // a2: (r,   k+4)
          "r"(__float_as_uint(a13.y)),   // a3: (r+8, k+4)
          "r"(__float_as_uint(b.x)),     // b0: (k,   n)
          "r"(__float_as_uint(b.y)));    // b1: (k+4, n)
}

__global__ __launch_bounds__(NT)
void conv15_hmma5_kernel(const float* __restrict__ X,
                         const float* __restrict__ Wt,
                         const float* __restrict__ bias,
                         float* __restrict__ out)
{
    __shared__ __align__(16) float sA[AROWS * APITCH];   // 31808 B
    __shared__ __align__(16) float sB[KH * 3 * 64];      // 11520 B

    const int tid  = threadIdx.x;
    const int warp = tid >> 5;
    const int lane = tid & 31;
    const int gx0  = blockIdx.x * TN;
    const int gy0  = blockIdx.y * TM;

    // ---- A fill (identical to R11) ----
    for (int i = tid; i < AROWS * KDIM; i += NT) {
        int r = i / KDIM, c = i - r * KDIM;
        int gy = gy0 + r; if (gy > H_IN - 1) gy = H_IN - 1;
        int gx = gx0 + c; if (gx > W_IN - 1) gx = W_IN - 1;
        int cc = c & 7;
        int cp = (c & ~7) | ((cc & 3) << 1) | (cc >> 2);
        sA[r * APITCH + cp] = __uint_as_float(tf32r(X[(size_t)gy * W_IN + gx]));
    }
    // ---- B fill (identical to R11) ----
    for (int i = tid; i < KH * 3 * 64; i += NT) {
        int e  = i & 63;          // nl*8 + k'
        int t  = i >> 6;          // ky*3 + jj
        int jj = t % 3, ky = t / 3;
        int nl = e >> 3, kp = e & 7;
        int kl = (kp >> 1) | ((kp & 1) << 2);    // inverse column permute
        int kx = jj * 8 + kl - nl;
        float v = (kx >= 0 && kx < KW) ? Wt[ky * KW + kx] : 0.0f;
        sB[i] = __uint_as_float(tf32r(v));
    }
    __syncthreads();

    float acc[2][4][4];
    #pragma unroll
    for (int mt = 0; mt < 2; mt++)
        #pragma unroll
        for (int nt = 0; nt < 4; nt++)
            #pragma unroll
            for (int f = 0; f < 4; f++) acc[mt][nt][f] = 0.0f;

    const int rA   = warp * 32 + (lane >> 2);   // fragment base row (mt=0)
    const int c2   = (lane & 3) * 2;            // permuted (k,k+4) pair col
    const int bOff = (lane >> 2) * 8 + c2;      // B block: [n][k']

    const float* ap0 = &sA[rA * APITCH + c2];   // mt=0 base row, ky=0

    float2 A02a[NCH], A13a[NCH];   // current mt=0 fragments
    float2 A02b[NCH], A13b[NCH];   // current mt=1 fragments
    float2 Bf[3], BfN[3];

    // ---- prologue: preload A(ky=0, mt=0) and Bf(ky=0) ----
    #pragma unroll
    for (int ch = 0; ch < NCH; ch++) {
        A02a[ch] = *(const float2*)(ap0 + 8 * ch);
        A13a[ch] = *(const float2*)(ap0 + 8 * APITCH + 8 * ch);
    }
    #pragma unroll
    for (int jj = 0; jj < 3; jj++)
        Bf[jj] = *(const float2*)&sB[jj * 64 + bOff];

    #pragma unroll 1
    for (int ky = 0; ky < KH; ky++) {
        // prefetch A(ky, mt=1)
        const float* apb = ap0 + 16 * APITCH;
        #pragma unroll
        for (int ch = 0; ch < NCH; ch++) {
            A02b[ch] = *(const float2*)(apb + 8 * ch);
            A13b[ch] = *(const float2*)(apb + 8 * APITCH + 8 * ch);
        }
        // prefetch Bf(ky+1)  (ky=14: reload current; discarded)
        const int kyn = (ky < KH - 1) ? ky + 1 : ky;
        #pragma unroll
        for (int jj = 0; jj < 3; jj++)
            BfN[jj] = *(const float2*)&sB[kyn * 192 + jj * 64 + bOff];

        // MMA block mt=0 (operands loaded last iteration / prologue)
        #pragma unroll
        for (int jj = 0; jj < 3; jj++)
            #pragma unroll
            for (int nt = 0; nt < 4; nt++)
                mma_tf32(acc[0][nt], A02a[nt + jj], A13a[nt + jj], Bf[jj]);

        // advance; prefetch A(ky+1, mt=0)  (ky=14: harmless in-bounds loads)
        ap0 += APITCH;
        #pragma unroll
        for (int ch = 0; ch < NCH; ch++) {
            A02a[ch] = *(const float2*)(ap0 + 8 * ch);
            A13a[ch] = *(const float2*)(ap0 + 8 * APITCH + 8 * ch);
        }

        // MMA block mt=1 (operands prefetched above, 12 MMAs ago)
        #pragma unroll
        for (int jj = 0; jj < 3; jj++)
            #pragma unroll
            for (int nt = 0; nt < 4; nt++)
                mma_tf32(acc[1][nt], A02b[nt + jj], A13b[nt + jj], Bf[jj]);

        // rotate B
        #pragma unroll
        for (int jj = 0; jj < 3; jj++) Bf[jj] = BfN[jj];
    }

    // ---- epilogue (identical to R11) ----
    const float bv = bias[0];
    #pragma unroll
    for (int mt = 0; mt < 2; mt++) {
        #pragma unroll
        for (int half = 0; half < 2; half++) {
            int oy = gy0 + warp * 32 + 16 * mt + (lane >> 2) + 8 * half;
            if (oy < OH) {
                #pragma unroll
                for (int nt = 0; nt < 4; nt++) {
                    int ox = gx0 + 8 * nt + c2;
                    if (ox < OW) {      // ox,OW even -> pair fits
                        float2 v;
                        v.x = acc[mt][nt][2 * half]     + bv;
                        v.y = acc[mt][nt][2 * half + 1] + bv;
                        *(float2*)&out[(size_t)oy * OW + ox] = v;
                    }
                }
            }
        }
    }
}

extern "C" void kernel_launch(void* const* d_in, const int* in_sizes, int n_in,
                              void* d_out, int out_size)
{
    const float* X    = (const float*)d_in[0];  // [4096,4096]
    const float* Wt   = (const float*)d_in[1];  // [15,15]
    const float* bias = (const float*)d_in[2];  // [1]
    float* out        = (float*)d_out;          // [4082,4082]

    dim3 grid((OW + TN - 1) / TN,    // 128
              (OH + TM - 1) / TM);   // 32
    conv15_hmma5_kernel<<<grid, NT>>>(X, Wt, bias, out);
}